// round 17
// baseline (speedup 1.0000x reference)
#include <cuda_runtime.h>
#include <cuda_bf16.h>
#include <math.h>

// Problem: B=128, T=128, K=8, H=3, HID=256, OUT=2
// grid 256: bb = blk>>1, r0 = (blk&1)*64. block 256, 2 CTAs/SM.
#define TTK 128
#define XP  68       // xst pad (floats)
#define HB  264      // h1 bf16 row pitch (528 B: LDSM conflict-free)
#define H2P 260      // hs2 fp32 row pitch
#define XST_FLOATS (32 * XP)                 // 2176
#define H1_ELEMS (64 * HB)                   // 16896 bf16
#define BUF_FLOATS (H1_ELEMS)                // h1hi+h1lo = 2*H1_ELEMS bf16 = H1_ELEMS floats... (see below)
// buf must hold max(attn views 9792 f, h1 hi+lo 16896 f, hs2 64*260=16640 f)
#define BUF_FLOATS_REAL 16896
#define SMEM_FLOATS (XST_FLOATS + BUF_FLOATS_REAL)       // 19072
#define SMEM_BYTES  (SMEM_FLOATS * 4)                    // 76288

typedef unsigned long long ull;

// Pre-converted W2 (transposed, bf16 hi/lo): W2T[n][k]
__device__ __nv_bfloat16 g_w2t_hi[256 * 256];
__device__ __nv_bfloat16 g_w2t_lo[256 * 256];

__device__ __forceinline__ ull pack2(float lo, float hi) {
    ull r; asm("mov.b64 %0,{%1,%2};" : "=l"(r) : "f"(lo), "f"(hi)); return r;
}
__device__ __forceinline__ void unpack2(ull v, float& lo, float& hi) {
    asm("mov.b64 {%0,%1},%2;" : "=f"(lo), "=f"(hi) : "l"(v));
}
__device__ __forceinline__ ull ffma2(ull a, ull b, ull c) {
    ull d; asm("fma.rn.f32x2 %0,%1,%2,%3;" : "=l"(d) : "l"(a), "l"(b), "l"(c));
    return d;
}
__device__ __forceinline__ ull mul2(ull a, ull b) {
    ull d; asm("mul.rn.f32x2 %0,%1,%2;" : "=l"(d) : "l"(a), "l"(b)); return d;
}
__device__ __forceinline__ void mma_bf16(float* c, const unsigned* a,
                                         const unsigned* b) {
    asm volatile(
        "mma.sync.aligned.m16n8k16.row.col.f32.bf16.bf16.f32 "
        "{%0,%1,%2,%3}, {%4,%5,%6,%7}, {%8,%9}, {%0,%1,%2,%3};"
        : "+f"(c[0]), "+f"(c[1]), "+f"(c[2]), "+f"(c[3])
        : "r"(a[0]), "r"(a[1]), "r"(a[2]), "r"(a[3]), "r"(b[0]), "r"(b[1]));
}
__device__ __forceinline__ void ldsm_x4(unsigned* r, unsigned addr) {
    asm volatile(
        "ldmatrix.sync.aligned.m8n8.x4.shared.b16 {%0,%1,%2,%3}, [%4];"
        : "=r"(r[0]), "=r"(r[1]), "=r"(r[2]), "=r"(r[3]) : "r"(addr));
}
__device__ __forceinline__ unsigned su32(const void* p) {
    unsigned a;
    asm("{.reg .u64 t; cvta.to.shared.u64 t, %1; cvt.u32.u64 %0, t;}"
        : "=r"(a) : "l"(p));
    return a;
}

// Accurate fp32 tanh (fast-math tanhf -> tanh.approx.f32, ~1e-4 ABS error;
// outputs are ~1e-3 scale -> need controlled error).
__device__ __forceinline__ float tanh_acc(float x) {
    float ax = fabsf(x);
    if (ax < 0.25f) {
        float x2 = x * x;
        float p = fmaf(x2, -0.05396825396825397f, 0.13333333333333333f);
        p = fmaf(x2, p, -0.3333333333333333f);
        p = fmaf(x2, p, 1.0f);
        return x * p;
    }
    float t = __expf(2.0f * fminf(ax, 44.0f));
    float r = (t - 1.0f) / (t + 1.0f);
    return copysignf(r, x);
}

// ---------------------------------------------------------------------------
// Prep: W2 [k][n] fp32 -> W2T hi/lo [n][k] bf16. block = n, thread = k.
// ---------------------------------------------------------------------------
__global__ __launch_bounds__(256) void w2_prep_kernel(const float* __restrict__ W2) {
    int n = blockIdx.x, k = threadIdx.x;
    float w = W2[k * 256 + n];
    __nv_bfloat16 hi = __float2bfloat16(w);
    g_w2t_hi[n * 256 + k] = hi;
    g_w2t_lo[n * 256 + k] = __float2bfloat16(w - __bfloat162float(hi));
}

__global__ __launch_bounds__(256, 2) void actor_kernel(
    const float* __restrict__ state, const float* __restrict__ noise,
    const float* __restrict__ Wq, const float* __restrict__ Wk,
    const float* __restrict__ Wv,
    const float* __restrict__ W1, const float* __restrict__ b1,
    const float* __restrict__ b2,
    const float* __restrict__ Wmu, const float* __restrict__ bmu,
    const float* __restrict__ Wls, const float* __restrict__ bls,
    float* __restrict__ out_action, float* __restrict__ out_logp) {
    extern __shared__ float sm[];
    float* xst = sm;                 // [32][XP] x-features transposed
    float* buf = sm + XST_FLOATS;    // union region
    // attention views (first ~39 KB of buf)
    float* sq = buf;                 // [3][128][8]
    float* sk = buf + 3072;
    float* sv = buf + 6144;
    float* ws = buf + 9216;          // 576
    // phase 1/2 views (bf16)
    __nv_bfloat16* h1hi = (__nv_bfloat16*)buf;      // [64][HB]
    __nv_bfloat16* h1lo = h1hi + H1_ELEMS;          // [64][HB]

    int tid  = threadIdx.x;
    int bb   = blockIdx.x >> 1;
    int r0   = (blockIdx.x & 1) * 64;   // local row window [r0, r0+64)

    // ---------------- projections: all 128 tokens' q/k/v ----------------
    if (tid < 192) {
        ws[tid]       = Wq[tid];
        ws[192 + tid] = Wk[tid];
        ws[384 + tid] = Wv[tid];
    }
    __syncthreads();
    {
        int tk = tid >> 1;              // token 0..127
        int cs = (tid & 1) * 12;        // 12 of 24 output cols
        float s[8];
#pragma unroll
        for (int d = 0; d < 8; d++) s[d] = state[(bb * TTK + tk) * 8 + d];
#pragma unroll
        for (int cc = 0; cc < 12; cc++) {
            int c = cs + cc, h = c >> 3, dc = c & 7;
            float aq = 0.f, ak = 0.f, av = 0.f;
#pragma unroll
            for (int d = 0; d < 8; d++) {
                aq = fmaf(s[d], ws[d * 24 + c], aq);
                ak = fmaf(s[d], ws[192 + d * 24 + c], ak);
                av = fmaf(s[d], ws[384 + d * 24 + c], av);
            }
            int off = (h * 128 + tk) * 8 + dc;
            sq[off] = aq; sk[off] = ak; sv[off] = av;
        }
        if ((tid & 1) == 0) {
            int il = tk - r0;
            if ((unsigned)il < 64u) {
#pragma unroll
                for (int d = 0; d < 8; d++) xst[(24 + d) * XP + il] = s[d];
            }
        }
    }
    __syncthreads();

    // ---------------- attention: 192 threads = 3 heads x 64 local queries ---
    // softmax shift-invariant -> no max pass; diagonal via predicated zero.
    if (tid < 192) {
        int h = tid >> 6, il = tid & 63, gi = r0 + il;
        const float* qb = sq + (h * 128 + gi) * 8;
        ulonglong2 q01 = *(const ulonglong2*)qb;
        ulonglong2 q23 = *(const ulonglong2*)(qb + 4);
        ull o0 = 0, o1 = 0, o2 = 0, o3 = 0;
        float ssum = 0.f;
        const float* skh = sk + h * 1024;
        const float* svh = sv + h * 1024;
        const float scale = 0.3535533905932738f;  // 1/sqrt(8)
#pragma unroll 2
        for (int j = 0; j < TTK; j++) {
            const float* kb = skh + j * 8;
            ulonglong2 k01 = *(const ulonglong2*)kb;
            ulonglong2 k23 = *(const ulonglong2*)(kb + 4);
            ull d2 = mul2(q01.x, k01.x);
            d2 = ffma2(q01.y, k01.y, d2);
            d2 = ffma2(q23.x, k23.x, d2);
            d2 = ffma2(q23.y, k23.y, d2);
            float lo, hi; unpack2(d2, lo, hi);
            float p = (j == gi) ? 0.f : __expf((lo + hi) * scale);
            ssum += p;
            ull pp = pack2(p, p);
            const float* vb = svh + j * 8;
            ulonglong2 v01 = *(const ulonglong2*)vb;
            ulonglong2 v23 = *(const ulonglong2*)(vb + 4);
            o0 = ffma2(pp, v01.x, o0);
            o1 = ffma2(pp, v01.y, o1);
            o2 = ffma2(pp, v23.x, o2);
            o3 = ffma2(pp, v23.y, o3);
        }
        float inv = 1.0f / ssum;
        const float* myv = svh + gi * 8;
        float ov[8];
        unpack2(o0, ov[0], ov[1]); unpack2(o1, ov[2], ov[3]);
        unpack2(o2, ov[4], ov[5]); unpack2(o3, ov[6], ov[7]);
#pragma unroll
        for (int d = 0; d < 8; d++)
            xst[(h * 8 + d) * XP + il] = ov[d] * inv - myv[d];
    }
    __syncthreads();

    // ---------------- phase 1: h1 = relu(x32 @ W1 + b1), emit bf16 hi/lo ----
    // thread = col n; 64 local rows = 32 packed pairs, k-outer, FFMA2.
    {
        int n = tid;
        float b1n = b1[n];
        ull acc[32];
        ull B = pack2(b1n, b1n);
#pragma unroll
        for (int p = 0; p < 32; p++) acc[p] = B;
#pragma unroll 4
        for (int k = 0; k < 32; k++) {
            float w = W1[k * 256 + n];
            ull wd = pack2(w, w);
            const float* xr = xst + k * XP;
#pragma unroll
            for (int p = 0; p < 16; p++) {
                ulonglong2 x = *(const ulonglong2*)(xr + 4 * p);
                acc[2 * p]     = ffma2(x.x, wd, acc[2 * p]);
                acc[2 * p + 1] = ffma2(x.y, wd, acc[2 * p + 1]);
            }
        }
        __syncthreads();   // attn views dead; buf becomes h1hi/h1lo
#pragma unroll
        for (int q = 0; q < 32; q++) {
            float v0, v1;
            unpack2(acc[q], v0, v1);
            v0 = fmaxf(v0, 0.f);
            v1 = fmaxf(v1, 0.f);
            __nv_bfloat16 h0 = __float2bfloat16(v0);
            __nv_bfloat16 h1v = __float2bfloat16(v1);
            h1hi[(2 * q) * HB + n]     = h0;
            h1hi[(2 * q + 1) * HB + n] = h1v;
            h1lo[(2 * q) * HB + n]     = __float2bfloat16(v0 - __bfloat162float(h0));
            h1lo[(2 * q + 1) * HB + n] = __float2bfloat16(v1 - __bfloat162float(h1v));
        }
    }
    __syncthreads();

    // ---------------- phase 2: h2 = relu(h1 @ W2 + b2), MMA, barrier-free ---
    // warp: rows m0=(w>>1)*16, cols nbase=(w&1)*128 (16 n-tiles of 8).
    // A (h1 hi/lo) via LDSM from smem; B via direct LDG.32 from pre-converted
    // transposed W2T bf16 (L1/L2-resident, shared by all CTAs). No barriers
    // inside the k-loop. Split: Ahi*Bhi + Alo*Bhi + Ahi*Blo.
    {
        int wid = tid >> 5, lane = tid & 31;
        int g = lane >> 2, t = lane & 3;
        int m0 = (wid >> 1) * 16;
        int nbase = (wid & 1) * 128;
        float c[16][4];
#pragma unroll
        for (int nt = 0; nt < 16; nt++)
#pragma unroll
            for (int e = 0; e < 4; e++) c[nt][e] = 0.f;

        unsigned a_hi = su32(h1hi) +
                        ((m0 + (lane & 15)) * HB + (lane >> 4) * 8) * 2;
        unsigned a_lo = a_hi + H1_ELEMS * 2;
        // B base: row nbase+g, k-offset 2t
        const __nv_bfloat16* bh_base = g_w2t_hi + (nbase + g) * 256 + 2 * t;
        const __nv_bfloat16* bl_base = g_w2t_lo + (nbase + g) * 256 + 2 * t;

        for (int kt = 0; kt < 16; kt++) {
            unsigned ahi[4], alo[4];
            ldsm_x4(ahi, a_hi + kt * 32);
            ldsm_x4(alo, a_lo + kt * 32);
            int kc = kt * 16;
#pragma unroll
            for (int nt = 0; nt < 16; nt++) {
                const __nv_bfloat16* ph = bh_base + nt * (8 * 256) + kc;
                const __nv_bfloat16* pl = bl_base + nt * (8 * 256) + kc;
                unsigned bh[2] = {*(const unsigned*)ph,
                                  *(const unsigned*)(ph + 8)};
                unsigned bl[2] = {*(const unsigned*)pl,
                                  *(const unsigned*)(pl + 8)};
                mma_bf16(c[nt], ahi, bh);
                mma_bf16(c[nt], alo, bh);
                mma_bf16(c[nt], ahi, bl);
            }
        }
        __syncthreads();   // all h1 reads done before epilogue aliases buf
        // epilogue: bias + relu -> hs2 fp32
        float* hs2 = buf;  // [64][H2P]
        int ra = m0 + g, rb = ra + 8;
#pragma unroll
        for (int nt = 0; nt < 16; nt++) {
            int col = nbase + 8 * nt + 2 * t;
            float2 bv = *(const float2*)(b2 + col);
            float2 s0 = {fmaxf(c[nt][0] + bv.x, 0.f),
                         fmaxf(c[nt][1] + bv.y, 0.f)};
            float2 s1 = {fmaxf(c[nt][2] + bv.x, 0.f),
                         fmaxf(c[nt][3] + bv.y, 0.f)};
            *(float2*)(hs2 + ra * H2P + col) = s0;
            *(float2*)(hs2 + rb * H2P + col) = s1;
        }
    }
    __syncthreads();

    // ---------------- phase 3: heads + rsample + log_prob -------------------
    // 4 threads/row, 64 k each, shfl-reduce in 4-lane groups.
    {
        int row = tid >> 2, sub = tid & 3;
        const float* hrow = buf + row * H2P + sub * 64;
        const float* wm = Wmu + sub * 128;
        const float* wl = Wls + sub * 128;
        float m0 = 0.f, m1 = 0.f, l0 = 0.f, l1 = 0.f;
#pragma unroll 8
        for (int k = 0; k < 64; k++) {
            float hv = hrow[k];
            float2 a = *(const float2*)(wm + 2 * k);
            float2 c = *(const float2*)(wl + 2 * k);
            m0 = fmaf(hv, a.x, m0);
            m1 = fmaf(hv, a.y, m1);
            l0 = fmaf(hv, c.x, l0);
            l1 = fmaf(hv, c.y, l1);
        }
#pragma unroll
        for (int d = 2; d > 0; d >>= 1) {
            m0 += __shfl_down_sync(0xFFFFFFFFu, m0, d);
            m1 += __shfl_down_sync(0xFFFFFFFFu, m1, d);
            l0 += __shfl_down_sync(0xFFFFFFFFu, l0, d);
            l1 += __shfl_down_sync(0xFFFFFFFFu, l1, d);
        }
        if (sub == 0) {
            m0 += bmu[0]; m1 += bmu[1]; l0 += bls[0]; l1 += bls[1];
            int grow = bb * TTK + r0 + row;
            float mu[2]  = {tanh_acc(m0), tanh_acc(m1)};
            float lsr[2] = {l0, l1};
            float lp = 0.0f;
#pragma unroll
            for (int o2 = 0; o2 < 2; o2++) {
                // log_std = -20 + 0.5*(2-(-20))*(tanh+1) = -20 + 11*(tanh+1)
                float ls = -20.0f + 11.0f * (tanh_acc(lsr[o2]) + 1.0f);
                float sd = __expf(ls);
                float nz = noise[grow * 2 + o2];
                float z  = mu[o2] + sd * nz;
                float a  = tanh_acc(z);
                out_action[grow * 2 + o2] = a;
                lp += (-0.5f * nz * nz - ls - 0.9189385332046727f)
                      - __logf(1.0f - a * a + 1e-7f);
            }
            out_logp[grow] = lp;
        }
    }
}

// ---------------------------------------------------------------------------
extern "C" void kernel_launch(void* const* d_in, const int* in_sizes, int n_in,
                              void* d_out, int out_size) {
    const float* state = (const float*)d_in[0];
    const float* noise = (const float*)d_in[1];
    const float* Wq  = (const float*)d_in[2];
    const float* Wk  = (const float*)d_in[3];
    const float* Wv  = (const float*)d_in[4];
    const float* W1  = (const float*)d_in[5];
    const float* b1  = (const float*)d_in[6];
    const float* W2  = (const float*)d_in[7];
    const float* b2  = (const float*)d_in[8];
    const float* Wmu = (const float*)d_in[9];
    const float* bmu = (const float*)d_in[10];
    const float* Wls = (const float*)d_in[11];
    const float* bls = (const float*)d_in[12];
    float* out = (float*)d_out;

    w2_prep_kernel<<<256, 256>>>(W2);
    cudaFuncSetAttribute(actor_kernel,
                         cudaFuncAttributeMaxDynamicSharedMemorySize, SMEM_BYTES);
    actor_kernel<<<256, 256, SMEM_BYTES>>>(
        state, noise, Wq, Wk, Wv, W1, b1, b2, Wmu, bmu, Wls, bls,
        out /*action*/, out + 32768 /*log_prob*/);
}